// round 1
// baseline (speedup 1.0000x reference)
#include <cuda_runtime.h>
#include <math.h>

// ---------------- problem constants ----------------
#define BATCH   8
#define CIN     512
#define COUT    512
#define WDIM    512
#define INS     64          // input spatial
#define Y1S     66          // conv output spatial (64 + 2*2 - 3 + 1)
#define PLANE   (Y1S*Y1S)   // 4356
#define UPS     138         // after up-FIR
#define OUTS    64

// ---------------- device scratch ----------------
__device__ float g_styles[BATCH*CIN];          // normalized styles
__device__ float g_filter[12];                 // shared up/down FIR taps
__device__ float g_wn[COUT*CIN*9];             // per-oc normalized weights
__device__ float g_W2[COUT*CIN];               // sum_k wn^2
__device__ float g_d[BATCH*COUT];              // demod coefficients
__device__ float g_y1[BATCH*COUT*PLANE];       // conv output (+bias, demod)

// ---------------- helpers ----------------
__device__ double bessel_i0(double x) {
    double t = x * x * 0.25;
    double term = 1.0, s = 1.0;
    for (int k = 1; k < 64; k++) {
        term *= t / ((double)k * (double)k);
        s += term;
        if (term < 1e-18 * s) break;
    }
    return s;
}

// ============ K0: filter design + styles GEMM + global style norm ============
__global__ void k0_styles_filter(const float* __restrict__ w,
                                 const float* __restrict__ A,
                                 const float* __restrict__ bias) {
    int i = threadIdx.x; // 0..511 (one per CIN channel)

    if (i == 0) {
        // kaiser beta for (numtaps=12, width=32, fs=128)
        const double PI = 3.14159265358979323846;
        double a = 2.285 * 11.0 * PI * (32.0 / 64.0) + 7.95;
        double beta;
        if (a > 50.0)      beta = 0.1102 * (a - 8.7);
        else if (a > 21.0) beta = 0.5842 * pow(a - 21.0, 0.4) + 0.07886 * (a - 21.0);
        else               beta = 0.0;
        double i0b = bessel_i0(beta);
        double h[12], sum = 0.0;
        const double c = 0.5; // cutoff/(fs/2)
        for (int n = 0; n < 12; n++) {
            double m = (double)n - 5.5;
            double sx = c * m;
            double sinc = (sx == 0.0) ? 1.0 : sin(PI * sx) / (PI * sx);
            double ratio = m / 5.5;
            double karg = beta * sqrt(fmax(0.0, 1.0 - ratio * ratio));
            h[n] = c * sinc * bessel_i0(karg) / i0b;
            sum += h[n];
        }
        for (int n = 0; n < 12; n++) g_filter[n] = (float)(h[n] / sum);
    }

    // styles[b][i] = sum_k w[b][k]*A[i][k] * (1/sqrt(512)) + bias[i]
    float acc[BATCH];
#pragma unroll
    for (int b = 0; b < BATCH; b++) acc[b] = 0.f;
    const float* Ai = A + (size_t)i * WDIM;
    for (int k = 0; k < WDIM; k++) {
        float av = Ai[k];
#pragma unroll
        for (int b = 0; b < BATCH; b++) acc[b] += w[b * WDIM + k] * av;
    }
    const float cc = 0.04419417382415922f; // 1/sqrt(512)
    float bi = bias[i];
    float p = 0.f;
#pragma unroll
    for (int b = 0; b < BATCH; b++) {
        acc[b] = acc[b] * cc + bi;
        p += acc[b] * acc[b];
    }
    __shared__ float red[512];
    red[i] = p;
    __syncthreads();
    for (int s = 256; s > 0; s >>= 1) {
        if (i < s) red[i] += red[i + s];
        __syncthreads();
    }
    float scale = rsqrtf(red[0] * (1.0f / (BATCH * CIN)));
#pragma unroll
    for (int b = 0; b < BATCH; b++) g_styles[b * CIN + i] = acc[b] * scale;
}

// ============ K1: weight normalization + W2 ============
__global__ void k1_wnorm(const float* __restrict__ cw) {
    int o = blockIdx.x, tid = threadIdx.x;
    const float* wo = cw + (size_t)o * (CIN * 9);
    __shared__ float red[256];
    float ss = 0.f;
    for (int t = tid; t < CIN * 9; t += 256) { float v = wo[t]; ss += v * v; }
    red[tid] = ss;
    __syncthreads();
    for (int s = 128; s > 0; s >>= 1) {
        if (tid < s) red[tid] += red[tid + s];
        __syncthreads();
    }
    float r = rsqrtf(red[0] * (1.0f / (CIN * 9)));
    for (int t = tid; t < CIN * 9; t += 256) g_wn[(size_t)o * (CIN * 9) + t] = wo[t] * r;
    float r2 = r * r;
    for (int i = tid; i < CIN; i += 256) {
        float s9 = 0.f;
#pragma unroll
        for (int k = 0; k < 9; k++) { float v = wo[i * 9 + k]; s9 += v * v; }
        g_W2[o * CIN + i] = s9 * r2;
    }
}

// ============ K2: demodulation coefficients ============
__global__ void k2_demod() {
    int b = blockIdx.x, o = threadIdx.x;
    __shared__ float s2[CIN];
    float sv = g_styles[b * CIN + o];
    s2[o] = sv * sv;
    __syncthreads();
    const float* w2 = g_W2 + (size_t)o * CIN;
    float acc = 0.f;
    for (int i = 0; i < CIN; i++) acc += s2[i] * w2[i];
    g_d[b * COUT + o] = rsqrtf(acc + 1e-8f);
}

// ============ K3: modulated conv (direct, fp32) ============
// grid (9 spatial tiles of 22x22, 32 oc-groups of 16, 8 batch), 128 threads.
// thread (i,j) in 11x11 computes a 2x2 pixel micro-tile for 16 out channels.
__global__ __launch_bounds__(128)
void k3_conv(const float* __restrict__ x, const float* __restrict__ cbias) {
    int tileid = blockIdx.x;      // 0..8
    int og = blockIdx.y;          // 0..31
    int b  = blockIdx.z;          // 0..7
    int tr = tileid / 3, tc = tileid % 3;
    int o0 = og * 16;
    int tid = threadIdx.x;

    __shared__ float xs[8][24][25];   // input tile (with 2-halo each side), padded stride
    __shared__ float ws[16][8][9];    // weights [oc][ic][k]

    float acc[64];
#pragma unroll
    for (int t = 0; t < 64; t++) acc[t] = 0.f;

    int r0 = tr * 22 - 2;
    int q0 = tc * 22 - 2;

    int ii = tid / 11, jj = tid % 11;     // compute mapping (valid if tid<121)
    int pr = 2 * ii, pc = 2 * jj;

    for (int c0 = 0; c0 < CIN; c0 += 8) {
        // load x tile (style-scaled, zero-padded)
        for (int t = tid; t < 8 * 24 * 24; t += 128) {
            int c = t / 576, rem = t % 576, r = rem / 24, q = rem % 24;
            int gr = r0 + r, gq = q0 + q;
            float v = 0.f;
            if (gr >= 0 && gr < INS && gq >= 0 && gq < INS)
                v = x[(((size_t)b * CIN + c0 + c) * INS + gr) * INS + gq] *
                    g_styles[b * CIN + c0 + c];
            xs[c][r][q] = v;
        }
        // load weights
        for (int t = tid; t < 1152; t += 128) {
            int oc = t / 72, rem = t % 72, c = rem / 9, k = rem % 9;
            ws[oc][c][k] = g_wn[((size_t)(o0 + oc) * CIN + c0 + c) * 9 + k];
        }
        __syncthreads();

        if (tid < 121) {
#pragma unroll 2
            for (int c = 0; c < 8; c++) {
                float xv[16];
#pragma unroll
                for (int r = 0; r < 4; r++)
#pragma unroll
                    for (int q = 0; q < 4; q++)
                        xv[r * 4 + q] = xs[c][pr + r][pc + q];
#pragma unroll
                for (int oc = 0; oc < 16; oc++) {
                    float w0 = ws[oc][c][0], w1 = ws[oc][c][1], w2 = ws[oc][c][2];
                    float w3 = ws[oc][c][3], w4 = ws[oc][c][4], w5 = ws[oc][c][5];
                    float w6 = ws[oc][c][6], w7 = ws[oc][c][7], w8 = ws[oc][c][8];
#pragma unroll
                    for (int dr = 0; dr < 2; dr++)
#pragma unroll
                        for (int dq = 0; dq < 2; dq++) {
                            float a = acc[oc * 4 + dr * 2 + dq];
                            a += w0 * xv[(dr + 0) * 4 + dq + 0];
                            a += w1 * xv[(dr + 0) * 4 + dq + 1];
                            a += w2 * xv[(dr + 0) * 4 + dq + 2];
                            a += w3 * xv[(dr + 1) * 4 + dq + 0];
                            a += w4 * xv[(dr + 1) * 4 + dq + 1];
                            a += w5 * xv[(dr + 1) * 4 + dq + 2];
                            a += w6 * xv[(dr + 2) * 4 + dq + 0];
                            a += w7 * xv[(dr + 2) * 4 + dq + 1];
                            a += w8 * xv[(dr + 2) * 4 + dq + 2];
                            acc[oc * 4 + dr * 2 + dq] = a;
                        }
                }
            }
        }
        __syncthreads();
    }

    if (tid < 121) {
#pragma unroll
        for (int oc = 0; oc < 16; oc++) {
            int o = o0 + oc;
            float dm = g_d[b * COUT + o];
            float bi = cbias[o];
#pragma unroll
            for (int dr = 0; dr < 2; dr++)
#pragma unroll
                for (int dq = 0; dq < 2; dq++) {
                    int P = tr * 22 + pr + dr;
                    int Q = tc * 22 + pc + dq;
                    g_y1[(((size_t)b * COUT + o) * Y1S + P) * Y1S + Q] =
                        acc[oc * 4 + dr * 2 + dq] * dm + bi;
                }
        }
    }
}

// ============ K4: fused upFIR -> lrelu/clamp -> downFIR (one block per plane) =
// smem: sy1 66*66 (4356) | vt 138*66 (9108, reused as dvt 64*138) | act 138*139
#define SM_SY1 0
#define SM_VT  4356
#define SM_ACT (4356 + 9108)
#define SM_FLOATS (4356 + 9108 + 138*139)

// polyphase up tap: src indexed [n>>1], valid if 0 <= n < 132
#define UTAPC(T, FI, LOADEXPR) { int n = rr + (T) - 9; if (n >= 0 && n < 132) { int jph = n >> 1; acc += (LOADEXPR) * fl[FI]; } }

__global__ __launch_bounds__(256)
void k4_fir(float* __restrict__ out) {
    int plane = blockIdx.x;              // b*512 + ch
    int tid = threadIdx.x;
    extern __shared__ float sm[];
    float* sy1 = sm + SM_SY1;
    float* vt  = sm + SM_VT;
    float* act = sm + SM_ACT;

    float fl[12];
#pragma unroll
    for (int k = 0; k < 12; k++) fl[k] = g_filter[k];

    // phase 1: load conv output plane
    const float* src = g_y1 + (size_t)plane * PLANE;
    for (int t = tid; t < PLANE; t += 256) sy1[t] = src[t];
    __syncthreads();

    // phase 2: vertical up-FIR (polyphase), gain 4 applied here. vt[138][66]
    for (int e = tid; e < UPS * Y1S; e += 256) {
        int rr = e / Y1S, i = e - rr * Y1S;
        float acc = 0.f;
        if ((rr & 1) == 0) { // even rows use odd taps
            UTAPC(1,  10, sy1[jph * Y1S + i]);
            UTAPC(3,   8, sy1[jph * Y1S + i]);
            UTAPC(5,   6, sy1[jph * Y1S + i]);
            UTAPC(7,   4, sy1[jph * Y1S + i]);
            UTAPC(9,   2, sy1[jph * Y1S + i]);
            UTAPC(11,  0, sy1[jph * Y1S + i]);
        } else {             // odd rows use even taps
            UTAPC(0,  11, sy1[jph * Y1S + i]);
            UTAPC(2,   9, sy1[jph * Y1S + i]);
            UTAPC(4,   7, sy1[jph * Y1S + i]);
            UTAPC(6,   5, sy1[jph * Y1S + i]);
            UTAPC(8,   3, sy1[jph * Y1S + i]);
            UTAPC(10,  1, sy1[jph * Y1S + i]);
        }
        vt[e] = 4.f * acc;
    }
    __syncthreads();

    // phase 3: horizontal up-FIR + lrelu*sqrt2 + clamp. act[138][139 stride]
    for (int e = tid; e < UPS * UPS; e += 256) {
        int r = e / UPS, rr = e - r * UPS; // rr = output column here
        const float* vr = vt + r * Y1S;
        float acc = 0.f;
        if ((rr & 1) == 0) {
            UTAPC(1,  10, vr[jph]);
            UTAPC(3,   8, vr[jph]);
            UTAPC(5,   6, vr[jph]);
            UTAPC(7,   4, vr[jph]);
            UTAPC(9,   2, vr[jph]);
            UTAPC(11,  0, vr[jph]);
        } else {
            UTAPC(0,  11, vr[jph]);
            UTAPC(2,   9, vr[jph]);
            UTAPC(4,   7, vr[jph]);
            UTAPC(6,   5, vr[jph]);
            UTAPC(8,   3, vr[jph]);
            UTAPC(10,  1, vr[jph]);
        }
        float a = (acc >= 0.f ? acc : 0.2f * acc) * 1.4142135623730951f;
        a = fminf(fmaxf(a, -256.f), 256.f);
        act[r * 139 + rr] = a;
    }
    __syncthreads();

    // phase 4: vertical down-FIR with stride-2 rows. dvt (in vt) [64][138]
    for (int e = tid; e < OUTS * UPS; e += 256) {
        int rr = e / UPS, j = e - rr * UPS;
        const float* ap = act + (2 * rr) * 139 + j;
        float acc = 0.f;
#pragma unroll
        for (int t = 0; t < 12; t++) acc += fl[11 - t] * ap[t * 139];
        vt[rr * UPS + j] = acc;
    }
    __syncthreads();

    // phase 5: horizontal down-FIR, stride 2, write output
    float* dst = out + (size_t)plane * (OUTS * OUTS);
    for (int e = tid; e < OUTS * OUTS; e += 256) {
        int rr = e / OUTS, cc = e - rr * OUTS;
        const float* dp = vt + rr * UPS + 2 * cc;
        float acc = 0.f;
#pragma unroll
        for (int t = 0; t < 12; t++) acc += fl[11 - t] * dp[t];
        dst[rr * OUTS + cc] = acc;
    }
}

// ============ launch ============
extern "C" void kernel_launch(void* const* d_in, const int* in_sizes, int n_in,
                              void* d_out, int out_size) {
    const float* x   = (const float*)d_in[0];
    const float* w   = (const float*)d_in[1];
    const float* A   = (const float*)d_in[2];
    const float* ab  = (const float*)d_in[3];
    const float* cw  = (const float*)d_in[4];
    const float* cb  = (const float*)d_in[5];
    float* out = (float*)d_out;

    cudaFuncSetAttribute(k4_fir, cudaFuncAttributeMaxDynamicSharedMemorySize,
                         SM_FLOATS * sizeof(float));

    k0_styles_filter<<<1, 512>>>(w, A, ab);
    k1_wnorm<<<COUT, 256>>>(cw);
    k2_demod<<<BATCH, COUT>>>();
    k3_conv<<<dim3(9, 32, BATCH), 128>>>(x, cb);
    k4_fir<<<BATCH * COUT, 256, SM_FLOATS * sizeof(float)>>>(out);
}